// round 1
// baseline (speedup 1.0000x reference)
#include <cuda_runtime.h>
#include <math.h>

#define NATOMS 24576
#define NB 256
#define NA 96
#define DIM 384
#define HID 192
#define FOUT 96
#define NSPEC 4
#define EMAX 786432
#define CUTOFF 5.2f

// ---------------- device scratch (static, no allocation) ----------------
__device__ float g_internal[NATOMS * FOUT];
__device__ float g_nbr[NATOMS * FOUT];
__device__ float g_merged[NATOMS * FOUT];
__device__ float g_decay[EMAX];
__device__ int   g_order[NATOMS];
__device__ int   g_off[8];          // [0..3] offsets, [4..7] counts
__device__ int   g_deg[NATOMS];
__device__ int   g_rowptr[NATOMS + 1];
__device__ int   g_cursor[NATOMS];
__device__ int   g_csrj[2 * EMAX];
__device__ float g_csrw[2 * EMAX];

__device__ __forceinline__ float gelu_tanh(float x) {
    float x3 = x * x * x;
    float t = tanhf(0.7978845608028654f * (x + 0.044715f * x3));
    return 0.5f * x * (1.0f + t);
}

// ---------------- species counting sort ----------------
__global__ void k_sort(const int* __restrict__ sp) {
    __shared__ int cnt[NSPEC];
    __shared__ int cur[NSPEC];
    int t = threadIdx.x;
    if (t < NSPEC) cnt[t] = 0;
    __syncthreads();
    for (int i = t; i < NATOMS; i += 1024) atomicAdd(&cnt[sp[i]], 1);
    __syncthreads();
    if (t == 0) {
        int acc = 0;
        for (int s = 0; s < NSPEC; s++) {
            cur[s] = acc;
            g_off[s] = acc;
            g_off[4 + s] = cnt[s];
            acc += cnt[s];
        }
    }
    __syncthreads();
    for (int i = t; i < NATOMS; i += 1024) {
        int p = atomicAdd(&cur[sp[i]], 1);
        g_order[p] = i;
    }
}

__global__ void k_zero_deg() {
    int i = blockIdx.x * 256 + threadIdx.x;
    if (i < NATOMS) g_deg[i] = 0;
}

__global__ void k_decay(const float* __restrict__ dist,
                        const float* __restrict__ pf,
                        const float* __restrict__ dfc, int E) {
    int e = blockIdx.x * 256 + threadIdx.x;
    if (e >= E) return;
    float d = dist[e];
    float x = (CUTOFF - d) * (1.0f / CUTOFF);
    x = fminf(fmaxf(x, 0.0f), 1.0f);
    float cut = x * x * x * (x * (6.0f * x - 15.0f) + 10.0f);
    float p = pf[0], f = dfc[0];
    g_decay[e] = p * p * expf(-f * f * d) * cut;
}

__global__ void k_count(const int* __restrict__ ai, int E) {
    int e = blockIdx.x * 256 + threadIdx.x;
    if (e >= E) return;
    atomicAdd(&g_deg[ai[e]], 1);
    atomicAdd(&g_deg[ai[E + e]], 1);
}

// single-block exclusive scan over NATOMS (=1024*24)
__global__ void k_scan() {
    __shared__ int part[1024];
    int t = threadIdx.x;
    int local[24];
    int s = 0;
    int base = t * 24;
    for (int k = 0; k < 24; k++) { local[k] = s; s += g_deg[base + k]; }
    part[t] = s;
    __syncthreads();
    for (int off = 1; off < 1024; off <<= 1) {
        int v = (t >= off) ? part[t - off] : 0;
        __syncthreads();
        part[t] += v;
        __syncthreads();
    }
    int pre = (t == 0) ? 0 : part[t - 1];
    for (int k = 0; k < 24; k++) {
        int v = pre + local[k];
        g_rowptr[base + k] = v;
        g_cursor[base + k] = v;
    }
    if (t == 1023) g_rowptr[NATOMS] = part[1023];
}

__global__ void k_fill(const int* __restrict__ ai, int E) {
    int e = blockIdx.x * 256 + threadIdx.x;
    if (e >= E) return;
    int i0 = ai[e], i1 = ai[E + e];
    float w = g_decay[e];
    int p0 = atomicAdd(&g_cursor[i0], 1);
    g_csrj[p0] = i1; g_csrw[p0] = w;
    int p1 = atomicAdd(&g_cursor[i1], 1);
    g_csrj[p1] = i0; g_csrw[p1] = w;
}

// ---------------- fused grouped MLP: internal & nbr ----------------
// smem layout (floats): Xs[16*64] | W1s[16*192] | hbuf[192*68] | big[18432]
//   big = W2s (stage B) then Wns[9216] + ibuf[96*68] (stage C)
#define SMEM_MLP_FLOATS 35584
__global__ void __launch_bounds__(256, 1)
k_mlp(const float* __restrict__ X, const float* __restrict__ W1,
      const float* __restrict__ W2, const float* __restrict__ Wn) {
    extern __shared__ float smf[];
    float* Xs   = smf;
    float* W1s  = smf + 1024;
    float* hbuf = smf + 4096;
    float* big  = smf + 17152;
    float* W2s  = big;
    float* Wns  = big;
    float* ibuf = big + 9216;

    __shared__ int rowsS[64];
    __shared__ int sBase, sNr, sSpec;

    int tid = threadIdx.x;
    if (tid == 0) {
        int bid = blockIdx.x, acc = 0, s = -1, base = 0, nr = 0;
        for (int q = 0; q < NSPEC; q++) {
            int c = g_off[4 + q];
            int tl = (c + 63) >> 6;
            if (bid < acc + tl) {
                s = q;
                int tile = bid - acc;
                base = g_off[q] + tile * 64;
                nr = c - tile * 64;
                if (nr > 64) nr = 64;
                break;
            }
            acc += tl;
        }
        sSpec = s; sBase = base; sNr = nr;
    }
    __syncthreads();
    int spec = sSpec;
    if (spec < 0) return;
    int base = sBase, nrows = sNr;
    if (tid < 64) rowsS[tid] = (tid < nrows) ? g_order[base + tid] : -1;
    __syncthreads();

    int tx = tid & 15, ty = tid >> 4;
    const float* W1g = W1 + spec * DIM * HID;

    float acc1[4][12];
    #pragma unroll
    for (int i = 0; i < 4; i++)
        #pragma unroll
        for (int j = 0; j < 12; j++) acc1[i][j] = 0.0f;

    int lr = tid >> 2;          // 0..63
    int lk = (tid & 3) << 2;    // 0,4,8,12
    int lrow = rowsS[lr];
    const float* xp = (lrow >= 0) ? (X + (long)lrow * DIM) : X;

    for (int k0 = 0; k0 < DIM; k0 += 16) {
        float4 v = make_float4(0.f, 0.f, 0.f, 0.f);
        if (lrow >= 0) v = *(const float4*)(xp + k0 + lk);
        Xs[(lk + 0) * 64 + lr] = v.x;
        Xs[(lk + 1) * 64 + lr] = v.y;
        Xs[(lk + 2) * 64 + lr] = v.z;
        Xs[(lk + 3) * 64 + lr] = v.w;
        #pragma unroll
        for (int i = 0; i < 3; i++) {
            int idx = tid + 256 * i;      // < 768 float4s
            int kk = idx / 48, c4 = idx % 48;
            *(float4*)&W1s[kk * 192 + c4 * 4] =
                *(const float4*)&W1g[(k0 + kk) * 192 + c4 * 4];
        }
        __syncthreads();
        #pragma unroll
        for (int kk = 0; kk < 16; kk++) {
            float4 a = *(const float4*)&Xs[kk * 64 + (ty << 2)];
            const float* wr = &W1s[kk * 192 + tx * 12];
            float4 b0 = *(const float4*)wr;
            float4 b1 = *(const float4*)(wr + 4);
            float4 b2 = *(const float4*)(wr + 8);
            float av[4] = {a.x, a.y, a.z, a.w};
            float bv[12] = {b0.x, b0.y, b0.z, b0.w, b1.x, b1.y, b1.z, b1.w,
                            b2.x, b2.y, b2.z, b2.w};
            #pragma unroll
            for (int i = 0; i < 4; i++)
                #pragma unroll
                for (int j = 0; j < 12; j++)
                    acc1[i][j] = fmaf(av[i], bv[j], acc1[i][j]);
        }
        __syncthreads();
    }

    // gelu -> hbuf[k][r]
    #pragma unroll
    for (int i = 0; i < 4; i++)
        #pragma unroll
        for (int j = 0; j < 12; j++)
            hbuf[(tx * 12 + j) * 68 + (ty * 4 + i)] = gelu_tanh(acc1[i][j]);

    // load W2 fully into smem
    const float* W2g = W2 + spec * HID * FOUT;
    #pragma unroll
    for (int i = 0; i < 18; i++) {
        int idx = tid + 256 * i;  // < 4608 float4s
        *(float4*)&W2s[idx * 4] = *(const float4*)&W2g[idx * 4];
    }
    __syncthreads();

    float acc2[4][6];
    #pragma unroll
    for (int i = 0; i < 4; i++)
        #pragma unroll
        for (int j = 0; j < 6; j++) acc2[i][j] = 0.0f;

    for (int k = 0; k < HID; k++) {
        float4 a = *(const float4*)&hbuf[k * 68 + (ty << 2)];
        const float* wr = &W2s[k * 96 + tx * 6];
        float bv[6];
        #pragma unroll
        for (int j = 0; j < 6; j++) bv[j] = wr[j];
        float av[4] = {a.x, a.y, a.z, a.w};
        #pragma unroll
        for (int i = 0; i < 4; i++)
            #pragma unroll
            for (int j = 0; j < 6; j++)
                acc2[i][j] = fmaf(av[i], bv[j], acc2[i][j]);
    }
    __syncthreads();  // done with W2s and hbuf

    // stage internal into ibuf[k][r]; load Wn
    #pragma unroll
    for (int i = 0; i < 4; i++)
        #pragma unroll
        for (int j = 0; j < 6; j++)
            ibuf[(tx * 6 + j) * 68 + (ty * 4 + i)] = acc2[i][j];
    const float* Wng = Wn + spec * FOUT * FOUT;
    #pragma unroll
    for (int i = 0; i < 9; i++) {
        int idx = tid + 256 * i;  // < 2304 float4s
        *(float4*)&Wns[idx * 4] = *(const float4*)&Wng[idx * 4];
    }
    __syncthreads();

    // coalesced write of internal
    for (int idx = tid; idx < 64 * 96; idx += 256) {
        int r = idx / 96, c = idx - r * 96;
        int row = rowsS[r];
        if (row >= 0) g_internal[row * 96 + c] = ibuf[c * 68 + r];
    }

    float acc3[4][6];
    #pragma unroll
    for (int i = 0; i < 4; i++)
        #pragma unroll
        for (int j = 0; j < 6; j++) acc3[i][j] = 0.0f;

    for (int k = 0; k < FOUT; k++) {
        float4 a = *(const float4*)&ibuf[k * 68 + (ty << 2)];
        const float* wr = &Wns[k * 96 + tx * 6];
        float bv[6];
        #pragma unroll
        for (int j = 0; j < 6; j++) bv[j] = wr[j];
        float av[4] = {a.x, a.y, a.z, a.w};
        #pragma unroll
        for (int i = 0; i < 4; i++)
            #pragma unroll
            for (int j = 0; j < 6; j++)
                acc3[i][j] = fmaf(av[i], bv[j], acc3[i][j]);
    }
    __syncthreads();

    // stage nbr into hbuf then coalesced write
    #pragma unroll
    for (int i = 0; i < 4; i++)
        #pragma unroll
        for (int j = 0; j < 6; j++)
            hbuf[(tx * 6 + j) * 68 + (ty * 4 + i)] = acc3[i][j];
    __syncthreads();
    for (int idx = tid; idx < 64 * 96; idx += 256) {
        int r = idx / 96, c = idx - r * 96;
        int row = rowsS[r];
        if (row >= 0) g_nbr[row * 96 + c] = hbuf[c * 68 + r];
    }
}

// ---------------- CSR gather: merged = sum decay * nbr[other] ----------------
__global__ void k_gather() {
    int gt = blockIdx.x * blockDim.x + threadIdx.x;
    int warp = gt >> 5, lane = gt & 31;
    if (warp >= NATOMS) return;
    int s = g_rowptr[warp], e = g_rowptr[warp + 1];
    float a0 = 0.f, a1 = 0.f, a2 = 0.f;
    int k = s;
    for (; k + 1 < e; k += 2) {
        int j0 = g_csrj[k], j1 = g_csrj[k + 1];
        float w0 = g_csrw[k], w1 = g_csrw[k + 1];
        const float* r0 = g_nbr + j0 * 96;
        const float* r1 = g_nbr + j1 * 96;
        a0 = fmaf(w0, r0[lane],      a0); a0 = fmaf(w1, r1[lane],      a0);
        a1 = fmaf(w0, r0[lane + 32], a1); a1 = fmaf(w1, r1[lane + 32], a1);
        a2 = fmaf(w0, r0[lane + 64], a2); a2 = fmaf(w1, r1[lane + 64], a2);
    }
    if (k < e) {
        int j = g_csrj[k];
        float w = g_csrw[k];
        const float* r = g_nbr + j * 96;
        a0 = fmaf(w, r[lane], a0);
        a1 = fmaf(w, r[lane + 32], a1);
        a2 = fmaf(w, r[lane + 64], a2);
    }
    float* m = g_merged + warp * 96;
    m[lane] = a0; m[lane + 32] = a1; m[lane + 64] = a2;
}

// ---------------- final head + charge redistribution ----------------
#define SMEM_FIN_FLOATS (9312 * 2 + 768 + 96 + 1)
__global__ void k_final(const int* __restrict__ sp, const float* __restrict__ tc,
                        const float* __restrict__ Wf, float* __restrict__ out,
                        int out_size) {
    extern __shared__ float smf[];
    float* sI   = smf;               // 96*97
    float* sM   = smf + 9312;        // 96*97
    float* wfS  = smf + 18624;       // 768
    float* preA = smf + 19392;       // 96
    float* totS = smf + 19488;       // 1
    int b = blockIdx.x, t = threadIdx.x;
    const float* gI = g_internal + b * (NA * FOUT);
    const float* gM = g_merged + b * (NA * FOUT);
    for (int idx = t; idx < NA * FOUT; idx += 256) {
        int r = idx / 96, c = idx - r * 96;
        sI[r * 97 + c] = gI[idx];
        sM[r * 97 + c] = gM[idx];
    }
    for (int idx = t; idx < 768; idx += 256) wfS[idx] = Wf[idx];
    __syncthreads();
    float pre = 0.0f;
    if (t < NA) {
        int i = b * NA + t;
        int s = sp[i];
        const float* wf = wfS + s * 192;
        #pragma unroll 8
        for (int c = 0; c < 96; c++)
            pre += sI[t * 97 + c] * wf[c] + sM[t * 97 + c] * wf[96 + c];
        preA[t] = pre;
    }
    __syncthreads();
    if (t == 0) {
        float ss = 0.f;
        for (int c = 0; c < NA; c++) ss += preA[c];
        totS[0] = (tc[b] - ss) * (1.0f / 96.0f);
    }
    __syncthreads();
    if (t < NA) {
        float ch = pre + totS[0];
        int i = b * NA + t;
        if (out_size >= 3 * NATOMS) {
            out[i] = (float)sp[i];
            out[NATOMS + i] = ch;
            out[2 * NATOMS + i] = pre;
        } else if (out_size >= 2 * NATOMS) {
            out[i] = ch;
            out[NATOMS + i] = pre;
        } else {
            out[i] = ch;
        }
    }
}

// ---------------- launch ----------------
extern "C" void kernel_launch(void* const* d_in, const int* in_sizes, int n_in,
                              void* d_out, int out_size) {
    const int*   sp   = (const int*)d_in[0];
    const float* X    = (const float*)d_in[1];
    const int*   ai   = (const int*)d_in[2];
    const float* dist = (const float*)d_in[3];
    const float* tc   = (const float*)d_in[4];
    const float* W1   = (const float*)d_in[5];
    const float* W2   = (const float*)d_in[6];
    const float* Wn   = (const float*)d_in[7];
    const float* Wf   = (const float*)d_in[8];
    const float* pf   = (const float*)d_in[9];
    const float* dfc  = (const float*)d_in[10];
    float* out = (float*)d_out;
    int E = in_sizes[3];
    if (E > EMAX) E = EMAX;

    cudaFuncSetAttribute(k_mlp, cudaFuncAttributeMaxDynamicSharedMemorySize,
                         SMEM_MLP_FLOATS * 4);
    cudaFuncSetAttribute(k_final, cudaFuncAttributeMaxDynamicSharedMemorySize,
                         SMEM_FIN_FLOATS * 4);

    int eb = (E + 255) / 256;
    k_sort<<<1, 1024>>>(sp);
    k_zero_deg<<<(NATOMS + 255) / 256, 256>>>();
    k_decay<<<eb, 256>>>(dist, pf, dfc, E);
    k_count<<<eb, 256>>>(ai, E);
    k_scan<<<1, 1024>>>();
    k_fill<<<eb, 256>>>(ai, E);
    k_mlp<<<(NATOMS / 64) + NSPEC, 256, SMEM_MLP_FLOATS * 4>>>(X, W1, W2, Wn);
    k_gather<<<(NATOMS * 32) / 256, 256>>>();
    k_final<<<NB, 256, SMEM_FIN_FLOATS * 4>>>(sp, tc, Wf, out, out_size);
}

// round 2
// speedup vs baseline: 1.2406x; 1.2406x over previous
#include <cuda_runtime.h>
#include <math.h>

#define NATOMS 24576
#define NB 256
#define NA 96
#define DIM 384
#define HID 192
#define FOUT 96
#define NSPEC 4
#define EMAX 786432
#define CUTOFF 5.2f

// ---------------- device scratch (static, no allocation) ----------------
__device__ float g_internal[NATOMS * FOUT];
__device__ float g_nbr[NATOMS * FOUT];
__device__ float g_merged[NATOMS * FOUT];
__device__ float g_decay[EMAX];
__device__ int   g_order[NATOMS];
__device__ int   g_off[8];          // [0..3] offsets, [4..7] counts
__device__ int   g_deg[NATOMS];
__device__ int   g_rowptr[NATOMS + 1];
__device__ int   g_cursor[NATOMS];
__device__ int   g_csrj[2 * EMAX];
__device__ float g_csrw[2 * EMAX];

__device__ __forceinline__ float gelu_tanh(float x) {
    float x3 = x * x * x;
    float t = tanhf(0.7978845608028654f * (x + 0.044715f * x3));
    return 0.5f * x * (1.0f + t);
}

// packed f32x2 helpers (sm_103a dual-rate fp32 path; PTX-only per SASS docs)
#define FMA2(acc, a, b) \
    asm("fma.rn.f32x2 %0, %1, %2, %0;" : "+l"(acc) : "l"(a), "l"(b))
#define PACK2(dst, lo, hi) \
    asm("mov.b64 %0, {%1, %2};" : "=l"(dst) : "f"(lo), "f"(hi))
#define UNPACK2(lo, hi, src) \
    asm("mov.b64 {%0, %1}, %2;" : "=f"(lo), "=f"(hi) : "l"(src))

// ---------------- species counting sort ----------------
__global__ void k_sort(const int* __restrict__ sp) {
    __shared__ int cnt[NSPEC];
    __shared__ int cur[NSPEC];
    int t = threadIdx.x;
    if (t < NSPEC) cnt[t] = 0;
    __syncthreads();
    for (int i = t; i < NATOMS; i += 1024) atomicAdd(&cnt[sp[i]], 1);
    __syncthreads();
    if (t == 0) {
        int acc = 0;
        for (int s = 0; s < NSPEC; s++) {
            cur[s] = acc;
            g_off[s] = acc;
            g_off[4 + s] = cnt[s];
            acc += cnt[s];
        }
    }
    __syncthreads();
    for (int i = t; i < NATOMS; i += 1024) {
        int p = atomicAdd(&cur[sp[i]], 1);
        g_order[p] = i;
    }
}

__global__ void k_zero_deg() {
    int i = blockIdx.x * 256 + threadIdx.x;
    if (i < NATOMS) g_deg[i] = 0;
}

// fused: decay weights + degree count (one pass over edges)
__global__ void k_decay_count(const float* __restrict__ dist,
                              const float* __restrict__ pf,
                              const float* __restrict__ dfc,
                              const int* __restrict__ ai, int E) {
    int e = blockIdx.x * 256 + threadIdx.x;
    if (e >= E) return;
    float d = dist[e];
    float x = (CUTOFF - d) * (1.0f / CUTOFF);
    x = fminf(fmaxf(x, 0.0f), 1.0f);
    float cut = x * x * x * (x * (6.0f * x - 15.0f) + 10.0f);
    float p = pf[0], f = dfc[0];
    g_decay[e] = p * p * expf(-f * f * d) * cut;
    atomicAdd(&g_deg[ai[e]], 1);
    atomicAdd(&g_deg[ai[E + e]], 1);
}

// single-block exclusive scan over NATOMS (=1024*24)
__global__ void k_scan() {
    __shared__ int part[1024];
    int t = threadIdx.x;
    int local[24];
    int s = 0;
    int base = t * 24;
    for (int k = 0; k < 24; k++) { local[k] = s; s += g_deg[base + k]; }
    part[t] = s;
    __syncthreads();
    for (int off = 1; off < 1024; off <<= 1) {
        int v = (t >= off) ? part[t - off] : 0;
        __syncthreads();
        part[t] += v;
        __syncthreads();
    }
    int pre = (t == 0) ? 0 : part[t - 1];
    for (int k = 0; k < 24; k++) {
        int v = pre + local[k];
        g_rowptr[base + k] = v;
        g_cursor[base + k] = v;
    }
    if (t == 1023) g_rowptr[NATOMS] = part[1023];
}

__global__ void k_fill(const int* __restrict__ ai, int E) {
    int e = blockIdx.x * 256 + threadIdx.x;
    if (e >= E) return;
    int i0 = ai[e], i1 = ai[E + e];
    float w = g_decay[e];
    int p0 = atomicAdd(&g_cursor[i0], 1);
    g_csrj[p0] = i1; g_csrw[p0] = w;
    int p1 = atomicAdd(&g_cursor[i1], 1);
    g_csrj[p1] = i0; g_csrw[p1] = w;
}

// ---------------- fused grouped MLP: internal & nbr (f32x2 packed) ----------
// smem layout (floats): Xs[16*64] | W1s[16*192] | hbuf[192*68] | big[18432]
//   big = W2s (stage B) then Wns[9216] + ibuf[96*68] (stage C)
#define SMEM_MLP_FLOATS 35584
__global__ void __launch_bounds__(256, 1)
k_mlp(const float* __restrict__ X, const float* __restrict__ W1,
      const float* __restrict__ W2, const float* __restrict__ Wn) {
    extern __shared__ float smf[];
    float* Xs   = smf;
    float* W1s  = smf + 1024;
    float* hbuf = smf + 4096;
    float* big  = smf + 17152;
    float* W2s  = big;
    float* Wns  = big;
    float* ibuf = big + 9216;

    __shared__ int rowsS[64];
    __shared__ int sBase, sNr, sSpec;

    int tid = threadIdx.x;
    if (tid == 0) {
        int bid = blockIdx.x, acc = 0, s = -1, base = 0, nr = 0;
        for (int q = 0; q < NSPEC; q++) {
            int c = g_off[4 + q];
            int tl = (c + 63) >> 6;
            if (bid < acc + tl) {
                s = q;
                int tile = bid - acc;
                base = g_off[q] + tile * 64;
                nr = c - tile * 64;
                if (nr > 64) nr = 64;
                break;
            }
            acc += tl;
        }
        sSpec = s; sBase = base; sNr = nr;
    }
    __syncthreads();
    int spec = sSpec;
    if (spec < 0) return;
    int base = sBase, nrows = sNr;
    if (tid < 64) rowsS[tid] = (tid < nrows) ? g_order[base + tid] : -1;
    __syncthreads();

    int tx = tid & 15, ty = tid >> 4;
    const float* W1g = W1 + spec * DIM * HID;

    // stage 1: [64,384] @ [384,192] -> gelu -> hbuf
    unsigned long long acc1[4][6];
    #pragma unroll
    for (int i = 0; i < 4; i++)
        #pragma unroll
        for (int j = 0; j < 6; j++) acc1[i][j] = 0ULL;

    int lr = tid >> 2;          // 0..63
    int lk = (tid & 3) << 2;    // 0,4,8,12
    int lrow = rowsS[lr];
    const float* xp = (lrow >= 0) ? (X + (long)lrow * DIM) : X;

    for (int k0 = 0; k0 < DIM; k0 += 16) {
        float4 v = make_float4(0.f, 0.f, 0.f, 0.f);
        if (lrow >= 0) v = *(const float4*)(xp + k0 + lk);
        Xs[(lk + 0) * 64 + lr] = v.x;
        Xs[(lk + 1) * 64 + lr] = v.y;
        Xs[(lk + 2) * 64 + lr] = v.z;
        Xs[(lk + 3) * 64 + lr] = v.w;
        #pragma unroll
        for (int i = 0; i < 3; i++) {
            int idx = tid + 256 * i;      // < 768 float4s
            int kk = idx / 48, c4 = idx % 48;
            *(float4*)&W1s[kk * 192 + c4 * 4] =
                *(const float4*)&W1g[(k0 + kk) * 192 + c4 * 4];
        }
        __syncthreads();
        #pragma unroll
        for (int kk = 0; kk < 16; kk++) {
            float4 a = *(const float4*)&Xs[kk * 64 + (ty << 2)];
            const float* wr = &W1s[kk * 192 + tx * 12];
            ulonglong2 p0 = *(const ulonglong2*)wr;        // 16B aligned
            ulonglong2 p1 = *(const ulonglong2*)(wr + 4);
            ulonglong2 p2 = *(const ulonglong2*)(wr + 8);
            unsigned long long bb[6] = {p0.x, p0.y, p1.x, p1.y, p2.x, p2.y};
            float av[4] = {a.x, a.y, a.z, a.w};
            #pragma unroll
            for (int i = 0; i < 4; i++) {
                unsigned long long ad;
                PACK2(ad, av[i], av[i]);
                #pragma unroll
                for (int j = 0; j < 6; j++)
                    FMA2(acc1[i][j], ad, bb[j]);
            }
        }
        __syncthreads();
    }

    // gelu -> hbuf[k][r]
    #pragma unroll
    for (int i = 0; i < 4; i++)
        #pragma unroll
        for (int j = 0; j < 6; j++) {
            float lo, hi;
            UNPACK2(lo, hi, acc1[i][j]);
            hbuf[(tx * 12 + 2 * j)     * 68 + (ty * 4 + i)] = gelu_tanh(lo);
            hbuf[(tx * 12 + 2 * j + 1) * 68 + (ty * 4 + i)] = gelu_tanh(hi);
        }

    // load W2 fully into smem
    const float* W2g = W2 + spec * HID * FOUT;
    #pragma unroll
    for (int i = 0; i < 18; i++) {
        int idx = tid + 256 * i;  // < 4608 float4s
        *(float4*)&W2s[idx * 4] = *(const float4*)&W2g[idx * 4];
    }
    __syncthreads();

    // stage 2: [64,192] @ [192,96] -> internal
    unsigned long long acc2[4][3];
    #pragma unroll
    for (int i = 0; i < 4; i++)
        #pragma unroll
        for (int j = 0; j < 3; j++) acc2[i][j] = 0ULL;

    for (int k = 0; k < HID; k++) {
        float4 a = *(const float4*)&hbuf[k * 68 + (ty << 2)];
        const unsigned long long* wp =
            (const unsigned long long*)&W2s[k * 96 + tx * 6];  // 8B aligned
        unsigned long long b0 = wp[0], b1 = wp[1], b2 = wp[2];
        float av[4] = {a.x, a.y, a.z, a.w};
        #pragma unroll
        for (int i = 0; i < 4; i++) {
            unsigned long long ad;
            PACK2(ad, av[i], av[i]);
            FMA2(acc2[i][0], ad, b0);
            FMA2(acc2[i][1], ad, b1);
            FMA2(acc2[i][2], ad, b2);
        }
    }
    __syncthreads();  // done with W2s and hbuf

    // stage internal into ibuf[k][r]; load Wn
    #pragma unroll
    for (int i = 0; i < 4; i++)
        #pragma unroll
        for (int j = 0; j < 3; j++) {
            float lo, hi;
            UNPACK2(lo, hi, acc2[i][j]);
            ibuf[(tx * 6 + 2 * j)     * 68 + (ty * 4 + i)] = lo;
            ibuf[(tx * 6 + 2 * j + 1) * 68 + (ty * 4 + i)] = hi;
        }
    const float* Wng = Wn + spec * FOUT * FOUT;
    #pragma unroll
    for (int i = 0; i < 9; i++) {
        int idx = tid + 256 * i;  // < 2304 float4s
        *(float4*)&Wns[idx * 4] = *(const float4*)&Wng[idx * 4];
    }
    __syncthreads();

    // coalesced write of internal
    for (int idx = tid; idx < 64 * 96; idx += 256) {
        int r = idx / 96, c = idx - r * 96;
        int row = rowsS[r];
        if (row >= 0) g_internal[row * 96 + c] = ibuf[c * 68 + r];
    }

    // stage 3: [64,96] @ [96,96] -> nbr
    unsigned long long acc3[4][3];
    #pragma unroll
    for (int i = 0; i < 4; i++)
        #pragma unroll
        for (int j = 0; j < 3; j++) acc3[i][j] = 0ULL;

    for (int k = 0; k < FOUT; k++) {
        float4 a = *(const float4*)&ibuf[k * 68 + (ty << 2)];
        const unsigned long long* wp =
            (const unsigned long long*)&Wns[k * 96 + tx * 6];
        unsigned long long b0 = wp[0], b1 = wp[1], b2 = wp[2];
        float av[4] = {a.x, a.y, a.z, a.w};
        #pragma unroll
        for (int i = 0; i < 4; i++) {
            unsigned long long ad;
            PACK2(ad, av[i], av[i]);
            FMA2(acc3[i][0], ad, b0);
            FMA2(acc3[i][1], ad, b1);
            FMA2(acc3[i][2], ad, b2);
        }
    }
    __syncthreads();

    // stage nbr into hbuf then coalesced write
    #pragma unroll
    for (int i = 0; i < 4; i++)
        #pragma unroll
        for (int j = 0; j < 3; j++) {
            float lo, hi;
            UNPACK2(lo, hi, acc3[i][j]);
            hbuf[(tx * 6 + 2 * j)     * 68 + (ty * 4 + i)] = lo;
            hbuf[(tx * 6 + 2 * j + 1) * 68 + (ty * 4 + i)] = hi;
        }
    __syncthreads();
    for (int idx = tid; idx < 64 * 96; idx += 256) {
        int r = idx / 96, c = idx - r * 96;
        int row = rowsS[r];
        if (row >= 0) g_nbr[row * 96 + c] = hbuf[c * 68 + r];
    }
}

// ---------------- CSR gather: merged = sum decay * nbr[other] ----------------
__global__ void k_gather() {
    int gt = blockIdx.x * blockDim.x + threadIdx.x;
    int warp = gt >> 5, lane = gt & 31;
    if (warp >= NATOMS) return;
    int s = g_rowptr[warp], e = g_rowptr[warp + 1];
    float a0 = 0.f, a1 = 0.f, a2 = 0.f;
    int k = s;
    for (; k + 3 < e; k += 4) {
        int j0 = g_csrj[k], j1 = g_csrj[k + 1];
        int j2 = g_csrj[k + 2], j3 = g_csrj[k + 3];
        float w0 = g_csrw[k], w1 = g_csrw[k + 1];
        float w2 = g_csrw[k + 2], w3 = g_csrw[k + 3];
        const float* r0 = g_nbr + j0 * 96;
        const float* r1 = g_nbr + j1 * 96;
        const float* r2 = g_nbr + j2 * 96;
        const float* r3 = g_nbr + j3 * 96;
        float x00 = r0[lane],      x01 = r1[lane],      x02 = r2[lane],      x03 = r3[lane];
        float x10 = r0[lane + 32], x11 = r1[lane + 32], x12 = r2[lane + 32], x13 = r3[lane + 32];
        float x20 = r0[lane + 64], x21 = r1[lane + 64], x22 = r2[lane + 64], x23 = r3[lane + 64];
        a0 = fmaf(w0, x00, a0); a0 = fmaf(w1, x01, a0);
        a0 = fmaf(w2, x02, a0); a0 = fmaf(w3, x03, a0);
        a1 = fmaf(w0, x10, a1); a1 = fmaf(w1, x11, a1);
        a1 = fmaf(w2, x12, a1); a1 = fmaf(w3, x13, a1);
        a2 = fmaf(w0, x20, a2); a2 = fmaf(w1, x21, a2);
        a2 = fmaf(w2, x22, a2); a2 = fmaf(w3, x23, a2);
    }
    for (; k < e; k++) {
        int j = g_csrj[k];
        float w = g_csrw[k];
        const float* r = g_nbr + j * 96;
        a0 = fmaf(w, r[lane], a0);
        a1 = fmaf(w, r[lane + 32], a1);
        a2 = fmaf(w, r[lane + 64], a2);
    }
    float* m = g_merged + warp * 96;
    m[lane] = a0; m[lane + 32] = a1; m[lane + 64] = a2;
}

// ---------------- final head + charge redistribution ----------------
#define SMEM_FIN_FLOATS (9312 * 2 + 768 + 96 + 1)
__global__ void k_final(const int* __restrict__ sp, const float* __restrict__ tc,
                        const float* __restrict__ Wf, float* __restrict__ out,
                        int out_size) {
    extern __shared__ float smf[];
    float* sI   = smf;               // 96*97
    float* sM   = smf + 9312;        // 96*97
    float* wfS  = smf + 18624;       // 768
    float* preA = smf + 19392;       // 96
    float* totS = smf + 19488;       // 1
    int b = blockIdx.x, t = threadIdx.x;
    const float* gI = g_internal + b * (NA * FOUT);
    const float* gM = g_merged + b * (NA * FOUT);
    for (int idx = t; idx < NA * FOUT; idx += 256) {
        int r = idx / 96, c = idx - r * 96;
        sI[r * 97 + c] = gI[idx];
        sM[r * 97 + c] = gM[idx];
    }
    for (int idx = t; idx < 768; idx += 256) wfS[idx] = Wf[idx];
    __syncthreads();
    float pre = 0.0f;
    if (t < NA) {
        int i = b * NA + t;
        int s = sp[i];
        const float* wf = wfS + s * 192;
        #pragma unroll 8
        for (int c = 0; c < 96; c++)
            pre += sI[t * 97 + c] * wf[c] + sM[t * 97 + c] * wf[96 + c];
        preA[t] = pre;
    }
    __syncthreads();
    if (t == 0) {
        float ss = 0.f;
        for (int c = 0; c < NA; c++) ss += preA[c];
        totS[0] = (tc[b] - ss) * (1.0f / 96.0f);
    }
    __syncthreads();
    if (t < NA) {
        float ch = pre + totS[0];
        int i = b * NA + t;
        if (out_size >= 3 * NATOMS) {
            out[i] = (float)sp[i];
            out[NATOMS + i] = ch;
            out[2 * NATOMS + i] = pre;
        } else if (out_size >= 2 * NATOMS) {
            out[i] = ch;
            out[NATOMS + i] = pre;
        } else {
            out[i] = ch;
        }
    }
}

// ---------------- launch ----------------
extern "C" void kernel_launch(void* const* d_in, const int* in_sizes, int n_in,
                              void* d_out, int out_size) {
    const int*   sp   = (const int*)d_in[0];
    const float* X    = (const float*)d_in[1];
    const int*   ai   = (const int*)d_in[2];
    const float* dist = (const float*)d_in[3];
    const float* tc   = (const float*)d_in[4];
    const float* W1   = (const float*)d_in[5];
    const float* W2   = (const float*)d_in[6];
    const float* Wn   = (const float*)d_in[7];
    const float* Wf   = (const float*)d_in[8];
    const float* pf   = (const float*)d_in[9];
    const float* dfc  = (const float*)d_in[10];
    float* out = (float*)d_out;
    int E = in_sizes[3];
    if (E > EMAX) E = EMAX;

    // one-time host resources (streams/events are not device memory)
    static cudaStream_t s_side = 0;
    static cudaEvent_t evF = 0, evJ = 0;
    static bool inited = false;
    if (!inited) {
        cudaStreamCreateWithFlags(&s_side, cudaStreamNonBlocking);
        cudaEventCreateWithFlags(&evF, cudaEventDisableTiming);
        cudaEventCreateWithFlags(&evJ, cudaEventDisableTiming);
        inited = true;
    }

    cudaFuncSetAttribute(k_mlp, cudaFuncAttributeMaxDynamicSharedMemorySize,
                         SMEM_MLP_FLOATS * 4);
    cudaFuncSetAttribute(k_final, cudaFuncAttributeMaxDynamicSharedMemorySize,
                         SMEM_FIN_FLOATS * 4);

    int eb = (E + 255) / 256;

    // fork side stream: CSR build (memory/atomic-bound) overlaps k_mlp (FMA-bound)
    cudaEventRecord(evF, 0);
    cudaStreamWaitEvent(s_side, evF, 0);
    k_zero_deg<<<(NATOMS + 255) / 256, 256, 0, s_side>>>();
    k_decay_count<<<eb, 256, 0, s_side>>>(dist, pf, dfc, ai, E);
    k_scan<<<1, 1024, 0, s_side>>>();
    k_fill<<<eb, 256, 0, s_side>>>(ai, E);
    cudaEventRecord(evJ, s_side);

    // main stream: sort -> MLP
    k_sort<<<1, 1024>>>(sp);
    k_mlp<<<(NATOMS / 64) + NSPEC, 256, SMEM_MLP_FLOATS * 4>>>(X, W1, W2, Wn);

    // join, then gather + final
    cudaStreamWaitEvent(0, evJ, 0);
    k_gather<<<(NATOMS * 32) / 256, 256>>>();
    k_final<<<NB, 256, SMEM_FIN_FLOATS * 4>>>(sp, tc, Wf, out, out_size);
}

// round 4
// speedup vs baseline: 1.3340x; 1.0753x over previous
#include <cuda_runtime.h>
#include <math.h>

#define NATOMS 24576
#define NB 256
#define NA 96
#define DIM 384
#define HID 192
#define FOUT 96
#define NSPEC 4
#define EMAX 786432
#define CUTOFF 5.2f

// ---------------- device scratch (static, no allocation) ----------------
__device__ float g_internal[NATOMS * FOUT];
__device__ float g_nbr[NATOMS * FOUT];
__device__ int   g_order[NATOMS];
__device__ int   g_off[8];          // [0..3] offsets, [4..7] counts
__device__ int   g_deg[NATOMS];
__device__ int   g_rowptr[NATOMS + 1];
__device__ int   g_cursor[NATOMS];
__device__ int2  g_csr[2 * EMAX];   // .x = neighbor idx, .y = weight bits

__device__ __forceinline__ float gelu_tanh(float x) {
    float x3 = x * x * x;
    float t = tanhf(0.7978845608028654f * (x + 0.044715f * x3));
    return 0.5f * x * (1.0f + t);
}

// packed f32x2 helpers (sm_103a dual-rate fp32 path; PTX-only per SASS docs)
#define FMA2(acc, a, b) \
    asm("fma.rn.f32x2 %0, %1, %2, %0;" : "+l"(acc) : "l"(a), "l"(b))
#define PACK2(dst, lo, hi) \
    asm("mov.b64 %0, {%1, %2};" : "=l"(dst) : "f"(lo), "f"(hi))
#define UNPACK2(lo, hi, src) \
    asm("mov.b64 {%0, %1}, %2;" : "=f"(lo), "=f"(hi) : "l"(src))

// ---------------- species counting sort ----------------
__global__ void k_sort(const int* __restrict__ sp) {
    __shared__ int cnt[NSPEC];
    __shared__ int cur[NSPEC];
    int t = threadIdx.x;
    if (t < NSPEC) cnt[t] = 0;
    __syncthreads();
    for (int i = t; i < NATOMS; i += 1024) atomicAdd(&cnt[sp[i]], 1);
    __syncthreads();
    if (t == 0) {
        int acc = 0;
        for (int s = 0; s < NSPEC; s++) {
            cur[s] = acc;
            g_off[s] = acc;
            g_off[4 + s] = cnt[s];
            acc += cnt[s];
        }
    }
    __syncthreads();
    for (int i = t; i < NATOMS; i += 1024) {
        int p = atomicAdd(&cur[sp[i]], 1);
        g_order[p] = i;
    }
}

__global__ void k_zero_deg() {
    int i = blockIdx.x * 256 + threadIdx.x;
    if (i < NATOMS) g_deg[i] = 0;
}

__global__ void k_count(const int* __restrict__ ai, int E) {
    int e = blockIdx.x * 256 + threadIdx.x;
    if (e >= E) return;
    atomicAdd(&g_deg[ai[e]], 1);
    atomicAdd(&g_deg[ai[E + e]], 1);
}

// single-block exclusive scan over NATOMS (=1024*24)
__global__ void k_scan() {
    __shared__ int part[1024];
    int t = threadIdx.x;
    int local[24];
    int s = 0;
    int base = t * 24;
    for (int k = 0; k < 24; k++) { local[k] = s; s += g_deg[base + k]; }
    part[t] = s;
    __syncthreads();
    for (int off = 1; off < 1024; off <<= 1) {
        int v = (t >= off) ? part[t - off] : 0;
        __syncthreads();
        part[t] += v;
        __syncthreads();
    }
    int pre = (t == 0) ? 0 : part[t - 1];
    for (int k = 0; k < 24; k++) {
        int v = pre + local[k];
        g_rowptr[base + k] = v;
        g_cursor[base + k] = v;
    }
    if (t == 1023) g_rowptr[NATOMS] = part[1023];
}

// fused: decay weight computation + CSR fill (packed int2 entries)
__global__ void k_fill(const int* __restrict__ ai, const float* __restrict__ dist,
                       const float* __restrict__ pf, const float* __restrict__ dfc,
                       int E) {
    int e = blockIdx.x * 256 + threadIdx.x;
    if (e >= E) return;
    float d = dist[e];
    float x = (CUTOFF - d) * (1.0f / CUTOFF);
    x = fminf(fmaxf(x, 0.0f), 1.0f);
    float cut = x * x * x * (x * (6.0f * x - 15.0f) + 10.0f);
    float p = pf[0], f = dfc[0];
    float w = p * p * expf(-f * f * d) * cut;
    int wb = __float_as_int(w);
    int i0 = ai[e], i1 = ai[E + e];
    int p0 = atomicAdd(&g_cursor[i0], 1);
    g_csr[p0] = make_int2(i1, wb);
    int p1 = atomicAdd(&g_cursor[i1], 1);
    g_csr[p1] = make_int2(i0, wb);
}

// ---------------- fused grouped MLP: internal & nbr (f32x2 packed) ----------
// smem layout (floats): Xs[16*64] | W1s[16*192] | hbuf[192*68] | big[18432]
//   big = W2s (stage B) then Wns[9216] + ibuf[96*68] (stage C)
#define SMEM_MLP_FLOATS 35584
__global__ void __launch_bounds__(256, 1)
k_mlp(const float* __restrict__ X, const float* __restrict__ W1,
      const float* __restrict__ W2, const float* __restrict__ Wn) {
    extern __shared__ float smf[];
    float* Xs   = smf;
    float* W1s  = smf + 1024;
    float* hbuf = smf + 4096;
    float* big  = smf + 17152;
    float* W2s  = big;
    float* Wns  = big;
    float* ibuf = big + 9216;

    __shared__ int rowsS[64];
    __shared__ int sBase, sNr, sSpec;

    int tid = threadIdx.x;
    if (tid == 0) {
        int bid = blockIdx.x, acc = 0, s = -1, base = 0, nr = 0;
        for (int q = 0; q < NSPEC; q++) {
            int c = g_off[4 + q];
            int tl = (c + 63) >> 6;
            if (bid < acc + tl) {
                s = q;
                int tile = bid - acc;
                base = g_off[q] + tile * 64;
                nr = c - tile * 64;
                if (nr > 64) nr = 64;
                break;
            }
            acc += tl;
        }
        sSpec = s; sBase = base; sNr = nr;
    }
    __syncthreads();
    int spec = sSpec;
    if (spec < 0) return;
    int base = sBase, nrows = sNr;
    if (tid < 64) rowsS[tid] = (tid < nrows) ? g_order[base + tid] : -1;
    __syncthreads();

    int tx = tid & 15, ty = tid >> 4;
    const float* W1g = W1 + spec * DIM * HID;

    // stage 1: [64,384] @ [384,192] -> gelu -> hbuf
    unsigned long long acc1[4][6];
    #pragma unroll
    for (int i = 0; i < 4; i++)
        #pragma unroll
        for (int j = 0; j < 6; j++) acc1[i][j] = 0ULL;

    int lr = tid >> 2;          // 0..63
    int lk = (tid & 3) << 2;    // 0,4,8,12
    int lrow = rowsS[lr];
    const float* xp = (lrow >= 0) ? (X + (long)lrow * DIM) : X;

    for (int k0 = 0; k0 < DIM; k0 += 16) {
        float4 v = make_float4(0.f, 0.f, 0.f, 0.f);
        if (lrow >= 0) v = *(const float4*)(xp + k0 + lk);
        Xs[(lk + 0) * 64 + lr] = v.x;
        Xs[(lk + 1) * 64 + lr] = v.y;
        Xs[(lk + 2) * 64 + lr] = v.z;
        Xs[(lk + 3) * 64 + lr] = v.w;
        #pragma unroll
        for (int i = 0; i < 3; i++) {
            int idx = tid + 256 * i;      // < 768 float4s
            int kk = idx / 48, c4 = idx % 48;
            *(float4*)&W1s[kk * 192 + c4 * 4] =
                *(const float4*)&W1g[(k0 + kk) * 192 + c4 * 4];
        }
        __syncthreads();
        #pragma unroll
        for (int kk = 0; kk < 16; kk++) {
            float4 a = *(const float4*)&Xs[kk * 64 + (ty << 2)];
            const float* wr = &W1s[kk * 192 + tx * 12];
            ulonglong2 p0 = *(const ulonglong2*)wr;        // 16B aligned
            ulonglong2 p1 = *(const ulonglong2*)(wr + 4);
            ulonglong2 p2 = *(const ulonglong2*)(wr + 8);
            unsigned long long bb[6] = {p0.x, p0.y, p1.x, p1.y, p2.x, p2.y};
            float av[4] = {a.x, a.y, a.z, a.w};
            #pragma unroll
            for (int i = 0; i < 4; i++) {
                unsigned long long ad;
                PACK2(ad, av[i], av[i]);
                #pragma unroll
                for (int j = 0; j < 6; j++)
                    FMA2(acc1[i][j], ad, bb[j]);
            }
        }
        __syncthreads();
    }

    // gelu -> hbuf[k][r]
    #pragma unroll
    for (int i = 0; i < 4; i++)
        #pragma unroll
        for (int j = 0; j < 6; j++) {
            float lo, hi;
            UNPACK2(lo, hi, acc1[i][j]);
            hbuf[(tx * 12 + 2 * j)     * 68 + (ty * 4 + i)] = gelu_tanh(lo);
            hbuf[(tx * 12 + 2 * j + 1) * 68 + (ty * 4 + i)] = gelu_tanh(hi);
        }

    // load W2 fully into smem
    const float* W2g = W2 + spec * HID * FOUT;
    #pragma unroll
    for (int i = 0; i < 18; i++) {
        int idx = tid + 256 * i;  // < 4608 float4s
        *(float4*)&W2s[idx * 4] = *(const float4*)&W2g[idx * 4];
    }
    __syncthreads();

    // stage 2: [64,192] @ [192,96] -> internal
    unsigned long long acc2[4][3];
    #pragma unroll
    for (int i = 0; i < 4; i++)
        #pragma unroll
        for (int j = 0; j < 3; j++) acc2[i][j] = 0ULL;

    for (int k = 0; k < HID; k++) {
        float4 a = *(const float4*)&hbuf[k * 68 + (ty << 2)];
        const unsigned long long* wp =
            (const unsigned long long*)&W2s[k * 96 + tx * 6];  // 8B aligned
        unsigned long long b0 = wp[0], b1 = wp[1], b2 = wp[2];
        float av[4] = {a.x, a.y, a.z, a.w};
        #pragma unroll
        for (int i = 0; i < 4; i++) {
            unsigned long long ad;
            PACK2(ad, av[i], av[i]);
            FMA2(acc2[i][0], ad, b0);
            FMA2(acc2[i][1], ad, b1);
            FMA2(acc2[i][2], ad, b2);
        }
    }
    __syncthreads();  // done with W2s and hbuf

    // stage internal into ibuf[k][r]; load Wn
    #pragma unroll
    for (int i = 0; i < 4; i++)
        #pragma unroll
        for (int j = 0; j < 3; j++) {
            float lo, hi;
            UNPACK2(lo, hi, acc2[i][j]);
            ibuf[(tx * 6 + 2 * j)     * 68 + (ty * 4 + i)] = lo;
            ibuf[(tx * 6 + 2 * j + 1) * 68 + (ty * 4 + i)] = hi;
        }
    const float* Wng = Wn + spec * FOUT * FOUT;
    #pragma unroll
    for (int i = 0; i < 9; i++) {
        int idx = tid + 256 * i;  // < 2304 float4s
        *(float4*)&Wns[idx * 4] = *(const float4*)&Wng[idx * 4];
    }
    __syncthreads();

    // coalesced write of internal
    for (int idx = tid; idx < 64 * 96; idx += 256) {
        int r = idx / 96, c = idx - r * 96;
        int row = rowsS[r];
        if (row >= 0) g_internal[row * 96 + c] = ibuf[c * 68 + r];
    }

    // stage 3: [64,96] @ [96,96] -> nbr
    unsigned long long acc3[4][3];
    #pragma unroll
    for (int i = 0; i < 4; i++)
        #pragma unroll
        for (int j = 0; j < 3; j++) acc3[i][j] = 0ULL;

    for (int k = 0; k < FOUT; k++) {
        float4 a = *(const float4*)&ibuf[k * 68 + (ty << 2)];
        const unsigned long long* wp =
            (const unsigned long long*)&Wns[k * 96 + tx * 6];
        unsigned long long b0 = wp[0], b1 = wp[1], b2 = wp[2];
        float av[4] = {a.x, a.y, a.z, a.w};
        #pragma unroll
        for (int i = 0; i < 4; i++) {
            unsigned long long ad;
            PACK2(ad, av[i], av[i]);
            FMA2(acc3[i][0], ad, b0);
            FMA2(acc3[i][1], ad, b1);
            FMA2(acc3[i][2], ad, b2);
        }
    }
    __syncthreads();

    // stage nbr into hbuf then coalesced write
    #pragma unroll
    for (int i = 0; i < 4; i++)
        #pragma unroll
        for (int j = 0; j < 3; j++) {
            float lo, hi;
            UNPACK2(lo, hi, acc3[i][j]);
            hbuf[(tx * 6 + 2 * j)     * 68 + (ty * 4 + i)] = lo;
            hbuf[(tx * 6 + 2 * j + 1) * 68 + (ty * 4 + i)] = hi;
        }
    __syncthreads();
    for (int idx = tid; idx < 64 * 96; idx += 256) {
        int r = idx / 96, c = idx - r * 96;
        int row = rowsS[r];
        if (row >= 0) g_nbr[row * 96 + c] = hbuf[c * 68 + r];
    }
}

// ------- fused CSR gather + final head + charge redistribution -------------
// one block = one molecule (96 atoms); 32 warps, each warp handles 3 atoms.
// merged never hits global memory: it is gathered into registers and dotted
// with Wf immediately via warp reduction.
__global__ void __launch_bounds__(1024, 2)
k_gather_final(const int* __restrict__ sp, const float* __restrict__ tc,
               const float* __restrict__ Wf, float* __restrict__ out,
               int out_size) {
    __shared__ float wfS[768];
    __shared__ float preA[NA];
    __shared__ float redS;
    int b = blockIdx.x, t = threadIdx.x;
    int warp = t >> 5, lane = t & 31;
    for (int idx = t; idx < 768; idx += 1024) wfS[idx] = Wf[idx];
    __syncthreads();

    #pragma unroll
    for (int rep = 0; rep < 3; rep++) {
        int a = warp + rep * 32;            // atom within molecule
        int i = b * NA + a;                 // global atom index
        int s = g_rowptr[i], e = g_rowptr[i + 1];
        float a0 = 0.f, a1 = 0.f, a2 = 0.f;
        int k = s;
        for (; k + 3 < e; k += 4) {
            int2 jw0 = g_csr[k],     jw1 = g_csr[k + 1];
            int2 jw2 = g_csr[k + 2], jw3 = g_csr[k + 3];
            const float* r0 = g_nbr + jw0.x * 96;
            const float* r1 = g_nbr + jw1.x * 96;
            const float* r2 = g_nbr + jw2.x * 96;
            const float* r3 = g_nbr + jw3.x * 96;
            float w0 = __int_as_float(jw0.y), w1 = __int_as_float(jw1.y);
            float w2 = __int_as_float(jw2.y), w3 = __int_as_float(jw3.y);
            float x00 = r0[lane],      x01 = r1[lane],      x02 = r2[lane],      x03 = r3[lane];
            float x10 = r0[lane + 32], x11 = r1[lane + 32], x12 = r2[lane + 32], x13 = r3[lane + 32];
            float x20 = r0[lane + 64], x21 = r1[lane + 64], x22 = r2[lane + 64], x23 = r3[lane + 64];
            a0 = fmaf(w0, x00, a0); a0 = fmaf(w1, x01, a0);
            a0 = fmaf(w2, x02, a0); a0 = fmaf(w3, x03, a0);
            a1 = fmaf(w0, x10, a1); a1 = fmaf(w1, x11, a1);
            a1 = fmaf(w2, x12, a1); a1 = fmaf(w3, x13, a1);
            a2 = fmaf(w0, x20, a2); a2 = fmaf(w1, x21, a2);
            a2 = fmaf(w2, x22, a2); a2 = fmaf(w3, x23, a2);
        }
        for (; k < e; k++) {
            int2 jw = g_csr[k];
            const float* r = g_nbr + jw.x * 96;
            float w = __int_as_float(jw.y);
            a0 = fmaf(w, r[lane], a0);
            a1 = fmaf(w, r[lane + 32], a1);
            a2 = fmaf(w, r[lane + 64], a2);
        }
        // dot with Wf[sp]: internal part + merged part, warp-reduced
        int spc = sp[i];
        const float* wf = wfS + spc * 192;
        const float* gI = g_internal + (long)i * 96;
        float pre = gI[lane]      * wf[lane]
                  + gI[lane + 32] * wf[lane + 32]
                  + gI[lane + 64] * wf[lane + 64]
                  + a0 * wf[96 + lane]
                  + a1 * wf[128 + lane]
                  + a2 * wf[160 + lane];
        #pragma unroll
        for (int off = 16; off > 0; off >>= 1)
            pre += __shfl_down_sync(0xFFFFFFFFu, pre, off);
        if (lane == 0) preA[a] = pre;
    }
    __syncthreads();
    if (warp == 0) {
        float v = (lane < 24) ? (preA[lane * 4] + preA[lane * 4 + 1] +
                                 preA[lane * 4 + 2] + preA[lane * 4 + 3]) : 0.f;
        #pragma unroll
        for (int off = 16; off > 0; off >>= 1)
            v += __shfl_down_sync(0xFFFFFFFFu, v, off);
        if (lane == 0) redS = (tc[b] - v) * (1.0f / 96.0f);
    }
    __syncthreads();
    if (t < NA) {
        float pre = preA[t];
        float ch = pre + redS;
        int i = b * NA + t;
        if (out_size >= 3 * NATOMS) {
            out[i] = (float)sp[i];
            out[NATOMS + i] = ch;
            out[2 * NATOMS + i] = pre;
        } else if (out_size >= 2 * NATOMS) {
            out[i] = ch;
            out[NATOMS + i] = pre;
        } else {
            out[i] = ch;
        }
    }
}

// ---------------- launch ----------------
extern "C" void kernel_launch(void* const* d_in, const int* in_sizes, int n_in,
                              void* d_out, int out_size) {
    const int*   sp   = (const int*)d_in[0];
    const float* X    = (const float*)d_in[1];
    const int*   ai   = (const int*)d_in[2];
    const float* dist = (const float*)d_in[3];
    const float* tc   = (const float*)d_in[4];
    const float* W1   = (const float*)d_in[5];
    const float* W2   = (const float*)d_in[6];
    const float* Wn   = (const float*)d_in[7];
    const float* Wf   = (const float*)d_in[8];
    const float* pf   = (const float*)d_in[9];
    const float* dfc  = (const float*)d_in[10];
    float* out = (float*)d_out;
    int E = in_sizes[3];
    if (E > EMAX) E = EMAX;

    // one-time host resources (streams/events are not device memory)
    static cudaStream_t s_side = 0;
    static cudaEvent_t evF = 0, evJ = 0;
    static bool inited = false;
    if (!inited) {
        cudaStreamCreateWithFlags(&s_side, cudaStreamNonBlocking);
        cudaEventCreateWithFlags(&evF, cudaEventDisableTiming);
        cudaEventCreateWithFlags(&evJ, cudaEventDisableTiming);
        inited = true;
    }

    cudaFuncSetAttribute(k_mlp, cudaFuncAttributeMaxDynamicSharedMemorySize,
                         SMEM_MLP_FLOATS * 4);

    int eb = (E + 255) / 256;

    // fork side stream: CSR build (memory/atomic-bound) overlaps k_mlp (FMA-bound)
    cudaEventRecord(evF, 0);
    cudaStreamWaitEvent(s_side, evF, 0);
    k_zero_deg<<<(NATOMS + 255) / 256, 256, 0, s_side>>>();
    k_count<<<eb, 256, 0, s_side>>>(ai, E);
    k_scan<<<1, 1024, 0, s_side>>>();
    k_fill<<<eb, 256, 0, s_side>>>(ai, dist, pf, dfc, E);
    cudaEventRecord(evJ, s_side);

    // main stream: sort -> MLP
    k_sort<<<1, 1024>>>(sp);
    k_mlp<<<(NATOMS / 64) + NSPEC, 256, SMEM_MLP_FLOATS * 4>>>(X, W1, W2, Wn);

    // join, then fused gather+final
    cudaStreamWaitEvent(0, evJ, 0);
    k_gather_final<<<NB, 1024>>>(sp, tc, Wf, out, out_size);
}